// round 10
// baseline (speedup 1.0000x reference)
#include <cuda_runtime.h>
#include <cstdint>

#define N_ROWS   262144
#define IN_D     256
#define OUT_D    256

#define THREADS  256          // 8 warps
#define TILE_M   64           // rows per CTA
#define TILE_N   256          // full output width per CTA
#define KCHUNK   32           // K elements per pipeline chunk (= one mma k-step)
#define NCHUNK   (IN_D / KCHUNK)   // 8

#define LDA      (IN_D + 16)       // 272B pitch for fp8 tiles
#define FP_PITCH 144               // bytes per row of fp32 chunk buf (32 floats + pad)
#define FBUF     (TILE_M * FP_PITCH)   // 9216

// smem layout (bytes)
#define SMEM_B     0                                 // 256 x 272 = 69632
#define SMEM_A     (SMEM_B + TILE_N * LDA)           // 69632 ; 64 x 272 = 17408
#define SMEM_F     (SMEM_A + TILE_M * LDA)           // 87040 ; 2 x 9216
#define SMEM_SC    (SMEM_F + 2 * FBUF)               // 105472
#define SMEM_TOTAL (SMEM_SC + 1024)                  // 106496

// ---------------- helpers ----------------
__device__ __forceinline__ uint32_t smem_u32(const void* p) {
    uint32_t a;
    asm("{ .reg .u64 t; cvta.to.shared.u64 t, %1; cvt.u32.u64 %0, t; }" : "=r"(a) : "l"(p));
    return a;
}
__device__ __forceinline__ void cp_async16(uint32_t dst, const void* src) {
    asm volatile("cp.async.cg.shared.global [%0], [%1], 16;" :: "r"(dst), "l"(src) : "memory");
}
#define CP_COMMIT()  asm volatile("cp.async.commit_group;" ::: "memory")
#define CP_WAIT(n)   asm volatile("cp.async.wait_group %0;" :: "n"(n) : "memory")

// sign(f) as e4m3 byte from fp32 bits: +1=0x38, -1=0xB8, 0=0x00 (sign(0)=0)
__device__ __forceinline__ uint32_t sgnb(uint32_t u) {
    uint32_t b = ((u >> 24) & 0x80u) | 0x38u;
    return (u & 0x7fffffffu) ? b : 0u;
}
__device__ __forceinline__ uint32_t pack_sgn4(float4 v) {
    uint32_t u0 = __float_as_uint(v.x), u1 = __float_as_uint(v.y);
    uint32_t u2 = __float_as_uint(v.z), u3 = __float_as_uint(v.w);
    return sgnb(u0) | (sgnb(u1) << 8) | (sgnb(u2) << 16) | (sgnb(u3) << 24);
}

// prepacked sign(weight) as e4m3 [OUT_D][IN_D]
__device__ __align__(16) uint8_t g_wb[OUT_D * IN_D];

__global__ void prepack_w_kernel(const float* __restrict__ w) {
    int idx = blockIdx.x * 256 + threadIdx.x;
    float f = w[idx];
    g_wb[idx] = (uint8_t)sgnb(__float_as_uint(f));
}

// ---------------- main kernel ----------------
__global__ void __launch_bounds__(THREADS, 2)
xnor_gemm_kernel(const float* __restrict__ x,
                 const float* __restrict__ scale,
                 float* __restrict__ out) {
    extern __shared__ char smem[];
    const uint32_t sb = smem_u32(smem);
    uint8_t* sB    = (uint8_t*)(smem + SMEM_B);
    uint8_t* sA    = (uint8_t*)(smem + SMEM_A);
    float*  sScale = (float*)(smem + SMEM_SC);

    const int tid  = threadIdx.x;
    const int lane = tid & 31;
    const int warp = tid >> 5;
    const int tig  = lane & 3;
    const int grp  = lane >> 2;
    const int mw   = warp & 1;     // 2 M-warps (32 rows each)
    const int nw   = warp >> 1;    // 4 N-warps (64 cols each)

    const size_t mbase = (size_t)blockIdx.x * TILE_M;

    // ---- scale (plain load; visible after first barrier) ----
    sScale[tid] = scale[tid];

    // ---- stage full weights [256][256] e4m3 via cp.async ----
    {
        #pragma unroll
        for (int i = 0; i < 16; i++) {
            int fid = tid + i * THREADS;      // 0..4095 (16B units)
            int row = fid >> 4;               // 16 x 16B per 256B row
            int c16 = fid & 15;
            cp_async16(sb + SMEM_B + row * LDA + c16 * 16,
                       g_wb + row * IN_D + c16 * 16);
        }
        CP_COMMIT();
    }

    // ---- prologue: chunks 0 and 1 of x (raw fp32) ----
    const float* xrow = x + mbase * IN_D;
    #pragma unroll
    for (int c = 0; c < 2; c++) {
        #pragma unroll
        for (int i = 0; i < 2; i++) {
            int fid = tid + i * THREADS;      // 0..511 (16B units)
            int row = fid >> 3;               // 8 x 16B per 32-float chunk row
            int c16 = fid & 7;
            cp_async16(sb + SMEM_F + c * FBUF + row * FP_PITCH + c16 * 16,
                       xrow + row * IN_D + c * KCHUNK + c16 * 4);
        }
        CP_COMMIT();
    }

    // ---- accumulators (f32) ----
    float acc[2][8][4];
    #pragma unroll
    for (int mi = 0; mi < 2; mi++)
        #pragma unroll
        for (int nf = 0; nf < 8; nf++)
            #pragma unroll
            for (int c = 0; c < 4; c++)
                acc[mi][nf][c] = 0.0f;

    const int aRowBase = mw * 32;
    const int nColBase = nw * 64;

    // ---- pipelined mainloop over 8 k-chunks ----
    #pragma unroll
    for (int c = 0; c < NCHUNK; c++) {
        // wait for chunk c (own copies visible to self)
        if (c < NCHUNK - 1) { CP_WAIT(1); } else { CP_WAIT(0); }

        // convert chunk c: this thread reads exactly the bytes it copied
        const int buf = c & 1;
        {
            #pragma unroll
            for (int i = 0; i < 2; i++) {
                int fid = tid + i * THREADS;
                int row = fid >> 3;
                int c16 = fid & 7;
                float4 v = *(const float4*)(smem + SMEM_F + buf * FBUF + row * FP_PITCH + c16 * 16);
                *(uint32_t*)(sA + row * LDA + c * KCHUNK + c16 * 4) = pack_sgn4(v);
            }
        }

        // prefetch chunk c+2 into the buffer just drained
        if (c < NCHUNK - 2) {
            const int nc = c + 2;
            #pragma unroll
            for (int i = 0; i < 2; i++) {
                int fid = tid + i * THREADS;
                int row = fid >> 3;
                int c16 = fid & 7;
                cp_async16(sb + SMEM_F + buf * FBUF + row * FP_PITCH + c16 * 16,
                           xrow + row * IN_D + nc * KCHUNK + c16 * 4);
            }
            CP_COMMIT();
        }

        __syncthreads();   // strip c (and, at c=0, weights/scale) visible to all

        // ---- 16 fp8 QMMA per warp for this k-step ----
        const int kOff = c * KCHUNK;
        unsigned int a[2][4];
        #pragma unroll
        for (int mi = 0; mi < 2; mi++) {
            const uint8_t* ap = sA + (aRowBase + mi * 16 + grp) * LDA + kOff + tig * 4;
            a[mi][0] = *(const unsigned int*)(ap);
            a[mi][1] = *(const unsigned int*)(ap + 8 * LDA);
            a[mi][2] = *(const unsigned int*)(ap + 16);
            a[mi][3] = *(const unsigned int*)(ap + 8 * LDA + 16);
        }
        #pragma unroll
        for (int nf = 0; nf < 8; nf++) {
            const uint8_t* bp = sB + (nColBase + nf * 8 + grp) * LDA + kOff + tig * 4;
            unsigned int b0 = *(const unsigned int*)(bp);
            unsigned int b1 = *(const unsigned int*)(bp + 16);
            #pragma unroll
            for (int mi = 0; mi < 2; mi++) {
                asm volatile(
                    "mma.sync.aligned.m16n8k32.row.col.f32.e4m3.e4m3.f32 "
                    "{%0,%1,%2,%3}, {%4,%5,%6,%7}, {%8,%9}, {%0,%1,%2,%3};"
                    : "+f"(acc[mi][nf][0]), "+f"(acc[mi][nf][1]),
                      "+f"(acc[mi][nf][2]), "+f"(acc[mi][nf][3])
                    : "r"(a[mi][0]), "r"(a[mi][1]), "r"(a[mi][2]), "r"(a[mi][3]),
                      "r"(b0), "r"(b1));
            }
        }
        if (c < NCHUNK - 1) __syncthreads();  // MMA reads of sA done before next convert
    }

    // ---- epilogue: y = acc * scale[col] ----
    const size_t outRow0 = mbase + mw * 32;
    #pragma unroll
    for (int mi = 0; mi < 2; mi++) {
        size_t r0 = outRow0 + mi * 16 + grp;
        #pragma unroll
        for (int nf = 0; nf < 8; nf++) {
            int col = nColBase + nf * 8 + tig * 2;
            float s0 = sScale[col];
            float s1 = sScale[col + 1];
            float2 v0 = make_float2(acc[mi][nf][0] * s0, acc[mi][nf][1] * s1);
            float2 v1 = make_float2(acc[mi][nf][2] * s0, acc[mi][nf][3] * s1);
            *(float2*)(out + r0 * OUT_D + col)       = v0;
            *(float2*)(out + (r0 + 8) * OUT_D + col) = v1;
        }
    }
}

extern "C" void kernel_launch(void* const* d_in, const int* in_sizes, int n_in,
                              void* d_out, int out_size) {
    const float* x     = (const float*)d_in[0];
    const float* w     = (const float*)d_in[1];
    const float* scale = (const float*)d_in[2];
    float* out = (float*)d_out;

    prepack_w_kernel<<<256, 256>>>(w);

    cudaFuncSetAttribute(xnor_gemm_kernel,
                         cudaFuncAttributeMaxDynamicSharedMemorySize, SMEM_TOTAL);
    xnor_gemm_kernel<<<N_ROWS / TILE_M, THREADS, SMEM_TOTAL>>>(x, scale, out);
}